// round 15
// baseline (speedup 1.0000x reference)
#include <cuda_runtime.h>
#include <cuda_bf16.h>

#define Bsz 64
#define Tsz 512
#define Dsz 1024
#define Usz 1024
#define Msz (Bsz * Tsz)
#define RCTA 64          // CTAs in recurrent kernel (one wave, co-resident)

// Double-buffered split-bf16 hidden state h[b][u], row-major [64][1024]
__device__ __align__(16) __nv_bfloat16 g_hbh[2][Bsz * Usz];
__device__ __align__(16) __nv_bfloat16 g_hbl[2][Bsz * Usz];
__device__ volatile unsigned int g_flag[RCTA];
__device__ volatile unsigned int g_go;

// Split-precision bf16 copies of x and W (written by cvt_split every call).
__device__ __align__(16) __nv_bfloat16 g_xhi[Msz * Dsz];   // 64 MB
__device__ __align__(16) __nv_bfloat16 g_xlo[Msz * Dsz];   // 64 MB
__device__ __align__(16) __nv_bfloat16 g_whi[Dsz * Usz];   // 2 MB
__device__ __align__(16) __nv_bfloat16 g_wlo[Dsz * Usz];   // 2 MB

// ---------------------------------------------------------------------------
// MMA / async helpers
// ---------------------------------------------------------------------------
__device__ __forceinline__ unsigned su32(const void* p)
{
    return (unsigned)__cvta_generic_to_shared(p);
}
__device__ __forceinline__ void ldsm4(unsigned* r, unsigned addr)
{
    asm volatile("ldmatrix.sync.aligned.m8n8.x4.shared.b16 {%0,%1,%2,%3}, [%4];"
                 : "=r"(r[0]), "=r"(r[1]), "=r"(r[2]), "=r"(r[3]) : "r"(addr));
}
__device__ __forceinline__ void ldsm4t(unsigned* r, unsigned addr)
{
    asm volatile("ldmatrix.sync.aligned.m8n8.x4.trans.shared.b16 {%0,%1,%2,%3}, [%4];"
                 : "=r"(r[0]), "=r"(r[1]), "=r"(r[2]), "=r"(r[3]) : "r"(addr));
}
__device__ __forceinline__ void ldsm2(unsigned* r, unsigned addr)
{
    asm volatile("ldmatrix.sync.aligned.m8n8.x2.shared.b16 {%0,%1}, [%2];"
                 : "=r"(r[0]), "=r"(r[1]) : "r"(addr));
}
__device__ __forceinline__ void mma16816(float* d, const unsigned* a, const unsigned* b)
{
    asm volatile(
        "mma.sync.aligned.m16n8k16.row.col.f32.bf16.bf16.f32 "
        "{%0,%1,%2,%3}, {%4,%5,%6,%7}, {%8,%9}, {%0,%1,%2,%3};"
        : "+f"(d[0]), "+f"(d[1]), "+f"(d[2]), "+f"(d[3])
        : "r"(a[0]), "r"(a[1]), "r"(a[2]), "r"(a[3]), "r"(b[0]), "r"(b[1]));
}
__device__ __forceinline__ void cpasync16(unsigned saddr, const void* gaddr)
{
    asm volatile("cp.async.cg.shared.global [%0], [%1], 16;"
                 :: "r"(saddr), "l"(gaddr));
}

// ---------------------------------------------------------------------------
// Reset scratch state so every graph replay is identical.
// ---------------------------------------------------------------------------
__global__ void init_kernel()
{
    int idx = blockIdx.x * blockDim.x + threadIdx.x;
    if (idx < Bsz * Usz) {
        g_hbh[0][idx] = __float2bfloat16(0.0f);
        g_hbl[0][idx] = __float2bfloat16(0.0f);
    }
    if (idx < RCTA) g_flag[idx] = 0u;
    if (idx == 0) g_go = 0u;
}

// ---------------------------------------------------------------------------
// Split fp32 -> (hi, lo) bf16 pair: v = hi + lo + O(2^-17 * v).
// ---------------------------------------------------------------------------
__global__ void cvt_split(const float* __restrict__ src,
                          __nv_bfloat16* __restrict__ hi,
                          __nv_bfloat16* __restrict__ lo, int n4)
{
    int i = blockIdx.x * blockDim.x + threadIdx.x;
    if (i >= n4) return;
    float4 v = ((const float4*)src)[i];
    __nv_bfloat16 h0 = __float2bfloat16(v.x);
    __nv_bfloat16 h1 = __float2bfloat16(v.y);
    __nv_bfloat16 h2 = __float2bfloat16(v.z);
    __nv_bfloat16 h3 = __float2bfloat16(v.w);
    __nv_bfloat16 l0 = __float2bfloat16(v.x - __bfloat162float(h0));
    __nv_bfloat16 l1 = __float2bfloat16(v.y - __bfloat162float(h1));
    __nv_bfloat16 l2 = __float2bfloat16(v.z - __bfloat162float(h2));
    __nv_bfloat16 l3 = __float2bfloat16(v.w - __bfloat162float(h3));
    __nv_bfloat162 ph0; ph0.x = h0; ph0.y = h1;
    __nv_bfloat162 ph1; ph1.x = h2; ph1.y = h3;
    __nv_bfloat162 pl0; pl0.x = l0; pl0.y = l1;
    __nv_bfloat162 pl1; pl1.x = l2; pl1.y = l3;
    ((__nv_bfloat162*)hi)[i * 2]     = ph0;
    ((__nv_bfloat162*)hi)[i * 2 + 1] = ph1;
    ((__nv_bfloat162*)lo)[i * 2]     = pl0;
    ((__nv_bfloat162*)lo)[i * 2 + 1] = pl1;
}

// ---------------------------------------------------------------------------
// Split-bf16 tensor-core SGEMM (proven R14): C = Ahi*Bhi + Ahi*Blo + Alo*Bhi.
// ---------------------------------------------------------------------------
__global__ __launch_bounds__(256)
void sgemm_mma(const __nv_bfloat16* __restrict__ Ahi,
               const __nv_bfloat16* __restrict__ Alo,
               const __nv_bfloat16* __restrict__ Bhi,
               const __nv_bfloat16* __restrict__ Blo,
               float* __restrict__ C)
{
    const int K = Dsz, N = Usz;
    __shared__ __align__(16) __nv_bfloat16 sAhi[128 * 40];
    __shared__ __align__(16) __nv_bfloat16 sAlo[128 * 40];
    __shared__ __align__(16) __nv_bfloat16 sBhi[32 * 136];
    __shared__ __align__(16) __nv_bfloat16 sBlo[32 * 136];

    const int tid  = threadIdx.x;
    const int lane = tid & 31;
    const int w    = tid >> 5;
    const int m0   = (w & 1) * 64;
    const int n0   = (w >> 1) * 32;
    const int row0 = blockIdx.y * 128;
    const int col0 = blockIdx.x * 128;

    const int arow = tid >> 1;
    const int ac   = (tid & 1) * 16;
    const int brow = tid >> 3;
    const int bc   = (tid & 7) * 16;

    const __nv_bfloat16* Aph = Ahi + (row0 + arow) * K + ac;
    const __nv_bfloat16* Apl = Alo + (row0 + arow) * K + ac;
    const __nv_bfloat16* Bph = Bhi + brow * N + col0 + bc;
    const __nv_bfloat16* Bpl = Blo + brow * N + col0 + bc;

    float acc[4][4][4];
#pragma unroll
    for (int i = 0; i < 4; ++i)
#pragma unroll
        for (int j = 0; j < 4; ++j)
#pragma unroll
            for (int q = 0; q < 4; ++q) acc[i][j][q] = 0.0f;

    uint4 rah0 = *(const uint4*)(Aph);
    uint4 rah1 = *(const uint4*)(Aph + 8);
    uint4 ral0 = *(const uint4*)(Apl);
    uint4 ral1 = *(const uint4*)(Apl + 8);
    uint4 rbh0 = *(const uint4*)(Bph);
    uint4 rbh1 = *(const uint4*)(Bph + 8);
    uint4 rbl0 = *(const uint4*)(Bpl);
    uint4 rbl1 = *(const uint4*)(Bpl + 8);

    for (int k0 = 0; k0 < K; k0 += 32) {
        *(uint4*)&sAhi[arow * 40 + ac]     = rah0;
        *(uint4*)&sAhi[arow * 40 + ac + 8] = rah1;
        *(uint4*)&sAlo[arow * 40 + ac]     = ral0;
        *(uint4*)&sAlo[arow * 40 + ac + 8] = ral1;
        *(uint4*)&sBhi[brow * 136 + bc]     = rbh0;
        *(uint4*)&sBhi[brow * 136 + bc + 8] = rbh1;
        *(uint4*)&sBlo[brow * 136 + bc]     = rbl0;
        *(uint4*)&sBlo[brow * 136 + bc + 8] = rbl1;
        __syncthreads();

        if (k0 + 32 < K) {
            rah0 = *(const uint4*)(Aph + k0 + 32);
            rah1 = *(const uint4*)(Aph + k0 + 40);
            ral0 = *(const uint4*)(Apl + k0 + 32);
            ral1 = *(const uint4*)(Apl + k0 + 40);
            rbh0 = *(const uint4*)(Bph + (k0 + 32) * N);
            rbh1 = *(const uint4*)(Bph + (k0 + 32) * N + 8);
            rbl0 = *(const uint4*)(Bpl + (k0 + 32) * N);
            rbl1 = *(const uint4*)(Bpl + (k0 + 32) * N + 8);
        }

#pragma unroll
        for (int kk = 0; kk < 32; kk += 16) {
            unsigned ah[4][4], al[4][4], bh[4][2], bl[4][2];
#pragma unroll
            for (int i = 0; i < 4; ++i) {
                int row = m0 + i * 16 + (lane & 15);
                int ck  = kk + ((lane >> 4) << 3);
                ldsm4(ah[i], su32(&sAhi[row * 40 + ck]));
                ldsm4(al[i], su32(&sAlo[row * 40 + ck]));
            }
#pragma unroll
            for (int nb = 0; nb < 2; ++nb) {
                int kr = kk + (((lane >> 3) & 1) << 3) + (lane & 7);
                int nc = n0 + nb * 16 + ((lane >> 4) << 3);
                unsigned r[4];
                ldsm4t(r, su32(&sBhi[kr * 136 + nc]));
                bh[nb * 2][0] = r[0]; bh[nb * 2][1] = r[1];
                bh[nb * 2 + 1][0] = r[2]; bh[nb * 2 + 1][1] = r[3];
                ldsm4t(r, su32(&sBlo[kr * 136 + nc]));
                bl[nb * 2][0] = r[0]; bl[nb * 2][1] = r[1];
                bl[nb * 2 + 1][0] = r[2]; bl[nb * 2 + 1][1] = r[3];
            }
#pragma unroll
            for (int i = 0; i < 4; ++i)
#pragma unroll
                for (int j = 0; j < 4; ++j) {
                    mma16816(acc[i][j], al[i], bh[j]);
                    mma16816(acc[i][j], ah[i], bl[j]);
                    mma16816(acc[i][j], ah[i], bh[j]);
                }
        }
        __syncthreads();
    }

#pragma unroll
    for (int i = 0; i < 4; ++i) {
#pragma unroll
        for (int j = 0; j < 4; ++j) {
            int r  = row0 + m0 + i * 16 + (lane >> 2);
            int c  = col0 + n0 + j * 8 + 2 * (lane & 3);
            *(float2*)&C[r * N + c]       = make_float2(acc[i][j][0], acc[i][j][1]);
            *(float2*)&C[(r + 8) * N + c] = make_float2(acc[i][j][2], acc[i][j][3]);
        }
    }
}

// ---------------------------------------------------------------------------
// Tensor-core recurrence. 64 CTAs x 256 thr (8 warps). CTA owns 16 output
// columns with FULL K=1024 (no cross-CTA/warp reduction). U slice resident in
// smem transposed+split (Ut[n][k] hi/lo, pad 1032). h kept as double-buffered
// bf16 hi/lo gmem [64][1024]; streamed per step in 4 K-chunks of 256 via
// cp.async into DB smem (pad 264). Warp w -> m16n8 tile: m0=(w&3)*16,
// n0=(w>>2)*8. 3-GEMM split per k-step, fp32 accum. Epilogue: +xk, relu,
// write fp32 out + bf16 hi/lo h_next. Grid barrier: proven master-CTA.
// ---------------------------------------------------------------------------
#define HCH  264                     // padded chunk row (256+8)
#define HBUF (Bsz * HCH * 2)         // one chunk buffer bytes (33792)
#define UPAD 1032

__global__ __launch_bounds__(256, 1)
void rnn_mma(const float* __restrict__ Wr, float* __restrict__ out)
{
    extern __shared__ char smraw[];
    __nv_bfloat16* sUh = (__nv_bfloat16*)smraw;            // [16][1032]
    __nv_bfloat16* sUl = sUh + 16 * UPAD;                  // [16][1032]
    __nv_bfloat16* sHh = sUl + 16 * UPAD;                  // [2][64][264]
    __nv_bfloat16* sHl = sHh + 2 * Bsz * HCH;              // [2][64][264]

    const int cta  = blockIdx.x;
    const int tid  = threadIdx.x;
    const int w    = tid >> 5;
    const int lane = tid & 31;
    const int c0   = cta * 16;         // this CTA's output columns
    const int m0   = (w & 3) * 16;     // warp M tile
    const int n0   = (w >> 2) * 8;     // warp N tile (local)

    // Stage U^T slice split into smem: sU[n][k] = split(Wr[k][c0+n]).
    for (int idx = tid; idx < 16 * Dsz; idx += 256) {
        int n = idx & 15;
        int k = idx >> 4;
        float u = Wr[k * Usz + c0 + n];
        __nv_bfloat16 hi = __float2bfloat16(u);
        __nv_bfloat16 lo = __float2bfloat16(u - __bfloat162float(hi));
        sUh[n * UPAD + k] = hi;
        sUl[n * UPAD + k] = lo;
    }
    __syncthreads();

    const unsigned sHh_u = su32(sHh);
    const unsigned sHl_u = su32(sHl);
    const unsigned sUh_u = su32(sUh);
    const unsigned sUl_u = su32(sUl);

    // ldmatrix lane addressing
    const int arow = m0 + (lane & 15);          // A row
    const int akc  = (lane >> 4) * 8;           // A k sub-col
    const int l16  = lane & 15;
    const int bn   = n0 + (l16 & 7);            // B n row (Ut)
    const int bk8  = (l16 >> 3) * 8;            // B k sub-col

    // epilogue lane mapping (m16n8 C fragment)
    const int er = m0 + (lane >> 2);            // batch row (and +8)
    const int ec = c0 + n0 + 2 * (lane & 3);    // global out column (even)

    for (int t = 0; t < Tsz; ++t) {
        const __nv_bfloat16* hh = g_hbh[t & 1];
        const __nv_bfloat16* hl = g_hbl[t & 1];
        __nv_bfloat16* nhh = g_hbh[(t + 1) & 1];
        __nv_bfloat16* nhl = g_hbl[(t + 1) & 1];

        // stage chunk c (K cols c*256..) into smem buffer c&1 via cp.async
        auto stage = [&](int c) {
            const int kc0 = c * 256;
            const unsigned bofs = (c & 1) ? (unsigned)HBUF : 0u;
#pragma unroll
            for (int i = 0; i < 8; ++i) {
                int s   = tid + i * 256;        // 0..2047
                int row = s >> 5;               // 0..63
                int sc  = s & 31;               // 0..31 (16B segs)
                unsigned so = bofs + (unsigned)(row * (HCH * 2) + sc * 16);
                const __nv_bfloat16* g = hh + row * Usz + kc0 + sc * 8;
                const __nv_bfloat16* gl = hl + row * Usz + kc0 + sc * 8;
                cpasync16(sHh_u + so, g);
                cpasync16(sHl_u + so, gl);
            }
            asm volatile("cp.async.commit_group;");
        };

        stage(0);

        float acc[4] = {0.0f, 0.0f, 0.0f, 0.0f};

#pragma unroll
        for (int c = 0; c < 4; ++c) {
            if (c < 3) stage(c + 1);
            if (c < 3) asm volatile("cp.async.wait_group 1;" ::: "memory");
            else       asm volatile("cp.async.wait_group 0;" ::: "memory");
            __syncthreads();

            const unsigned bofs = (c & 1) ? (unsigned)HBUF : 0u;
            const unsigned abase = bofs + (unsigned)(arow * (HCH * 2) + akc * 2);
            const unsigned ubo = (unsigned)(bn * (UPAD * 2) + (c * 256 + bk8) * 2);
#pragma unroll
            for (int ks = 0; ks < 16; ++ks) {
                unsigned ah[4], al[4], bh[2], bl[2];
                ldsm4(ah, sHh_u + abase + ks * 32);
                ldsm4(al, sHl_u + abase + ks * 32);
                ldsm2(bh, sUh_u + ubo + ks * 32);
                ldsm2(bl, sUl_u + ubo + ks * 32);
                mma16816(acc, al, bh);   // lo*hi
                mma16816(acc, ah, bl);   // hi*lo
                mma16816(acc, ah, bh);   // hi*hi
            }
            __syncthreads();             // chunk buffer free for reuse
        }

        // Epilogue: + xk (out), relu, write fp32 out + split h_next.
        {
            const int go0 = (er * Tsz + t) * Usz + ec;
            const int go1 = ((er + 8) * Tsz + t) * Usz + ec;
            float2 xk0 = *(const float2*)&out[go0];
            float2 xk1 = *(const float2*)&out[go1];
            float v00 = fmaxf(acc[0] + xk0.x, 0.0f);
            float v01 = fmaxf(acc[1] + xk0.y, 0.0f);
            float v10 = fmaxf(acc[2] + xk1.x, 0.0f);
            float v11 = fmaxf(acc[3] + xk1.y, 0.0f);
            *(float2*)&out[go0] = make_float2(v00, v01);
            *(float2*)&out[go1] = make_float2(v10, v11);

            const int h0 = er * Usz + ec;
            const int h1 = (er + 8) * Usz + ec;
            __nv_bfloat162 ph, pl;
            ph.x = __float2bfloat16(v00);
            ph.y = __float2bfloat16(v01);
            pl.x = __float2bfloat16(v00 - __bfloat162float(ph.x));
            pl.y = __float2bfloat16(v01 - __bfloat162float(ph.y));
            *(__nv_bfloat162*)&nhh[h0] = ph;
            *(__nv_bfloat162*)&nhl[h0] = pl;
            ph.x = __float2bfloat16(v10);
            ph.y = __float2bfloat16(v11);
            pl.x = __float2bfloat16(v10 - __bfloat162float(ph.x));
            pl.y = __float2bfloat16(v11 - __bfloat162float(ph.y));
            *(__nv_bfloat162*)&nhh[h1] = ph;
            *(__nv_bfloat162*)&nhl[h1] = pl;
        }

        // ---- grid barrier (proven: flag array + master-CTA broadcast) ----
        unsigned int tv = (unsigned int)t + 1u;
        __syncthreads();
        if (tid == 0) {
            __threadfence();
            g_flag[cta] = tv;
        }
        if (cta == 0) {
            if (tid < RCTA) {
                while (g_flag[tid] < tv) { }
            }
            __syncthreads();
            if (tid == 0) {
                __threadfence();
                g_go = tv;
            }
        }
        if (tid == 0) {
            while (g_go < tv) { }
            __threadfence();
        }
        __syncthreads();
    }
}

// ---------------------------------------------------------------------------
extern "C" void kernel_launch(void* const* d_in, const int* in_sizes, int n_in,
                              void* d_out, int out_size)
{
    (void)in_sizes; (void)n_in; (void)out_size;
    const float* x  = (const float*)d_in[0];   // [64,512,1024]
    const float* W  = (const float*)d_in[1];   // [1024,1024]
    const float* Wr = (const float*)d_in[2];   // [1024,1024]
    float* out = (float*)d_out;                // [64,512,1024]

    __nv_bfloat16 *xhi, *xlo, *whi, *wlo;
    cudaGetSymbolAddress((void**)&xhi, g_xhi);
    cudaGetSymbolAddress((void**)&xlo, g_xlo);
    cudaGetSymbolAddress((void**)&whi, g_whi);
    cudaGetSymbolAddress((void**)&wlo, g_wlo);

    // smem: Ut hi/lo (2*33024) + h chunks hi/lo DB (2*2*33792) = 201216 B
    const int rnn_smem = 2 * 16 * UPAD * 2 + 2 * 2 * Bsz * HCH * 2;
    cudaFuncSetAttribute(rnn_mma,
                         cudaFuncAttributeMaxDynamicSharedMemorySize, rnn_smem);

    init_kernel<<<(Bsz * Usz + 255) / 256, 256>>>();

    // Split x and W into bf16 hi/lo pairs
    cvt_split<<<(Msz * Dsz / 4 + 255) / 256, 256>>>(x, xhi, xlo, Msz * Dsz / 4);
    cvt_split<<<(Dsz * Usz / 4 + 255) / 256, 256>>>(W, whi, wlo, Dsz * Usz / 4);

    // xk = x @ W via split-bf16 tensor cores
    dim3 g(Usz / 128, Msz / 128);              // 8 x 256 CTAs
    sgemm_mma<<<g, 256>>>(xhi, xlo, whi, wlo, out);

    // Sequential scan via split-bf16 tensor cores, in place on out
    rnn_mma<<<RCTA, 256, rnn_smem>>>(Wr, out);
}